// round 2
// baseline (speedup 1.0000x reference)
#include <cuda_runtime.h>
#include <math.h>

#define NN 50000
#define NE 800000
#define D  128
#define RB 64
#define NEG 0.2f
#define BNEPS 1e-5f

// ---------------- static device scratch (no allocations allowed) ----------------
__device__ float g_xl[NN * D];
__device__ float g_xr[NN * D];
__device__ float g_out[NN * D];
__device__ float g_xbuf[NN * D];
__device__ float g_e[NE];
__device__ int   g_srcs[NE];
__device__ int   g_off[NN + 1];
__device__ int   g_cur[NN];
__device__ int   g_cnt[NN];
__device__ float g_colsum[D];
__device__ float g_colsq[D];
__device__ int   g_is64;

// ---------------- edge dtype probe ----------------
// int64 little-endian values < 2^31 have zero upper words at odd positions.
// int32 data at odd positions holds other node indices (rarely all zero).
__global__ void k_detect(const int* __restrict__ w) {
    if (threadIdx.x == 0 && blockIdx.x == 0) {
        int allz = 1;
        for (int i = 1; i < 64; i += 2)
            if (w[i] != 0) allz = 0;
        g_is64 = allz;
    }
}

__device__ __forceinline__ int edge_at(const int* __restrict__ w, int pos, int is64) {
    return is64 ? w[(long long)pos * 2] : w[pos];
}

// ---------------- CSR build (once per call; edges are an input) ----------------
__global__ void k_zero_cnt() {
    int i = blockIdx.x * 256 + threadIdx.x;
    if (i < NN) g_cnt[i] = 0;
}

__global__ void k_hist(const int* __restrict__ ei) {
    int e = blockIdx.x * 256 + threadIdx.x;
    if (e < NE) {
        int dst = edge_at(ei, NE + e, g_is64);
        atomicAdd(&g_cnt[dst], 1);
    }
}

// single-block exclusive scan over 50000 counts
__global__ void k_scan() {
    __shared__ int sh[1024];
    const int CH = 49;  // 1024*49 = 50176 >= NN
    int tid = threadIdx.x;
    int lo = tid * CH;
    int hi = min(lo + CH, NN);
    int s = 0;
    for (int i = lo; i < hi; i++) s += g_cnt[i];
    sh[tid] = s;
    __syncthreads();
    for (int o = 1; o < 1024; o <<= 1) {
        int v = (tid >= o) ? sh[tid - o] : 0;
        __syncthreads();
        sh[tid] += v;
        __syncthreads();
    }
    int run = sh[tid] - s;  // exclusive prefix at start of chunk
    for (int i = lo; i < hi; i++) {
        g_off[i] = run;
        g_cur[i] = run;
        run += g_cnt[i];
    }
    if (tid == 1023) g_off[NN] = sh[1023];
}

__global__ void k_scatter(const int* __restrict__ ei) {
    int e = blockIdx.x * 256 + threadIdx.x;
    if (e < NE) {
        int is64 = g_is64;
        int src = edge_at(ei, e, is64);
        int dst = edge_at(ei, NE + e, is64);
        int pos = atomicAdd(&g_cur[dst], 1);
        g_srcs[pos] = src;
    }
}

// ---------------- fused dual GEMM: xl = x@Wl, xr = x@Wr ----------------
// 256 threads: tid<128 -> xl column tid, tid>=128 -> xr column tid-128.
// Both W matrices (128KB) + a 64-row x tile (32KB) in dynamic smem.
// All x-tile loads in the k-loop are warp-uniform (broadcast, conflict-free).
__global__ void __launch_bounds__(256, 1)
k_gemm(const float* __restrict__ xin, const float* __restrict__ Wl,
       const float* __restrict__ Wr) {
    extern __shared__ float sm[];
    float* sW = sm;            // [2][128][128]
    float* sX = sm + 32768;    // [RB][128]
    int tid = threadIdx.x;
    const float* xsrc = xin ? xin : g_xbuf;
    {
        float4* d = (float4*)sW;
        const float4* a = (const float4*)Wl;
        const float4* b = (const float4*)Wr;
        for (int i = tid; i < 4096; i += 256) {
            d[i] = a[i];
            d[4096 + i] = b[i];
        }
    }
    int row0 = blockIdx.x * RB;
    {
        float4* d = (float4*)sX;
        for (int i = tid; i < RB * 32; i += 256) {
            int r = i >> 5;
            int row = row0 + r;
            float4 v = (row < NN) ? ((const float4*)xsrc)[row * 32 + (i & 31)]
                                  : make_float4(0.f, 0.f, 0.f, 0.f);
            d[i] = v;
        }
    }
    __syncthreads();

    const float* Ws = sW + ((tid >> 7) << 14);
    int col = tid & 127;
    float acc[RB];
#pragma unroll
    for (int r = 0; r < RB; r++) acc[r] = 0.f;

    for (int kg = 0; kg < 32; kg++) {
        float w0 = Ws[(kg * 4 + 0) * 128 + col];
        float w1 = Ws[(kg * 4 + 1) * 128 + col];
        float w2 = Ws[(kg * 4 + 2) * 128 + col];
        float w3 = Ws[(kg * 4 + 3) * 128 + col];
#pragma unroll
        for (int r = 0; r < RB; r++) {
            float4 xv = *(const float4*)(sX + r * 128 + kg * 4);
            acc[r] = fmaf(xv.x, w0, acc[r]);
            acc[r] = fmaf(xv.y, w1, acc[r]);
            acc[r] = fmaf(xv.z, w2, acc[r]);
            acc[r] = fmaf(xv.w, w3, acc[r]);
        }
    }
    float* outp = (tid < 128) ? g_xl : g_xr;
#pragma unroll
    for (int r = 0; r < RB; r++) {
        int row = row0 + r;
        if (row < NN) outp[row * 128 + col] = acc[r];
    }
}

// ---------------- per-node GATv2 attention + aggregation (warp per node) ----------------
__global__ void k_node(const float* __restrict__ att, const float* __restrict__ bias) {
    int gw = (blockIdx.x * blockDim.x + threadIdx.x) >> 5;
    int lane = threadIdx.x & 31;
    if (gw >= NN) return;
    int beg = g_off[gw], end = g_off[gw + 1];

    const float4 xrv = *(const float4*)(g_xr + gw * 128 + lane * 4);
    const float4 av = *(const float4*)(att + lane * 4);

    // pass A: edge scores e = leaky_relu(xl[src]+xr[dst]) . att, track max
    float m = -1e30f;
    for (int p = beg; p < end; p++) {
        int s = g_srcs[p];
        float4 v = *(const float4*)(g_xl + s * 128 + lane * 4);
        float t0 = v.x + xrv.x; t0 = t0 > 0.f ? t0 : NEG * t0;
        float t1 = v.y + xrv.y; t1 = t1 > 0.f ? t1 : NEG * t1;
        float t2 = v.z + xrv.z; t2 = t2 > 0.f ? t2 : NEG * t2;
        float t3 = v.w + xrv.w; t3 = t3 > 0.f ? t3 : NEG * t3;
        float d = t0 * av.x + t1 * av.y + t2 * av.z + t3 * av.w;
#pragma unroll
        for (int o = 16; o > 0; o >>= 1) d += __shfl_xor_sync(0xffffffffu, d, o);
        if (lane == 0) g_e[p] = d;
        m = fmaxf(m, d);
    }
    __syncwarp();

    // pass B: a = exp(e - max), sum
    float sum = 0.f;
    for (int p = beg + lane; p < end; p += 32) {
        float a = __expf(g_e[p] - m);
        g_e[p] = a;
        sum += a;
    }
#pragma unroll
    for (int o = 16; o > 0; o >>= 1) sum += __shfl_xor_sync(0xffffffffu, sum, o);
    __syncwarp();
    float inv = 1.f / (sum + 1e-16f);

    // pass C: out = sum alpha * xl[src] + bias
    float ax = 0.f, ay = 0.f, az = 0.f, aw = 0.f;
    for (int p = beg; p < end; p++) {
        int s = g_srcs[p];
        float w = g_e[p] * inv;
        float4 v = *(const float4*)(g_xl + s * 128 + lane * 4);
        ax = fmaf(w, v.x, ax);
        ay = fmaf(w, v.y, ay);
        az = fmaf(w, v.z, az);
        aw = fmaf(w, v.w, aw);
    }
    float4 bv = *(const float4*)(bias + lane * 4);
    float4 o4;
    o4.x = ax + bv.x; o4.y = ay + bv.y; o4.z = az + bv.z; o4.w = aw + bv.w;
    *(float4*)(g_out + gw * 128 + lane * 4) = o4;
}

// ---------------- BatchNorm stats + BN->GELU apply ----------------
__global__ void k_zero_cols() {
    g_colsum[threadIdx.x] = 0.f;
    g_colsq[threadIdx.x] = 0.f;
}

__global__ void k_bn() {
    int col = threadIdx.x;  // 128 threads
    float s = 0.f, q = 0.f;
    for (int r = blockIdx.x; r < NN; r += gridDim.x) {
        float v = g_out[r * 128 + col];
        s += v;
        q += v * v;
    }
    atomicAdd(&g_colsum[col], s);
    atomicAdd(&g_colsq[col], q);
}

__global__ void k_bnapply(const float* __restrict__ gamma,
                          const float* __restrict__ beta,
                          float* __restrict__ dptr) {
    int i = blockIdx.x * 256 + threadIdx.x;
    if (i >= NN * D) return;
    int col = i & 127;
    const float invN = 1.f / (float)NN;
    float mu = g_colsum[col] * invN;
    float var = g_colsq[col] * invN - mu * mu;
    float v = g_out[i];
    float y = gamma[col] * (v - mu) * rsqrtf(var + BNEPS) + beta[col];
    float g = 0.5f * y * (1.f + erff(y * 0.70710678118654752f));
    float* dst = dptr ? dptr : g_xbuf;
    dst[i] = g;
}

// ---------------- launch ----------------
extern "C" void kernel_launch(void* const* d_in, const int* in_sizes, int n_in,
                              void* d_out, int out_size) {
    const float* x = (const float*)d_in[0];
    const int* ei = (const int*)d_in[1];   // int32 words; int64 handled via probe
    const float* Wl = (const float*)d_in[2];
    const float* Wr = (const float*)d_in[3];
    const float* att = (const float*)d_in[4];
    const float* bias = (const float*)d_in[5];
    const float* gamma = (const float*)d_in[6];
    const float* beta = (const float*)d_in[7];
    float* outp = (float*)d_out;

    cudaFuncSetAttribute(k_gemm, cudaFuncAttributeMaxDynamicSharedMemorySize, 163840);

    // CSR by dst (edges are a fixed input, but rebuild every call: no caching)
    k_detect<<<1, 32>>>(ei);
    k_zero_cnt<<<(NN + 255) / 256, 256>>>();
    k_hist<<<(NE + 255) / 256, 256>>>(ei);
    k_scan<<<1, 1024>>>();
    k_scatter<<<(NE + 255) / 256, 256>>>(ei);

    const int gemm_blocks = (NN + RB - 1) / RB;
    for (int l = 0; l < 3; l++) {
        const float* xin = (l == 0) ? x : nullptr;  // nullptr -> g_xbuf inside kernel
        k_gemm<<<gemm_blocks, 256, 163840>>>(xin, Wl + l * D * D, Wr + l * D * D);
        k_node<<<(NN + 7) / 8, 256>>>(att + l * D, bias + l * D);
        k_zero_cols<<<1, 128>>>();
        k_bn<<<256, 128>>>();
        float* dst = (l == 2) ? outp : nullptr;  // nullptr -> g_xbuf inside kernel
        k_bnapply<<<(NN * D + 255) / 256, 256>>>(gamma + l * D, beta + l * D, dst);
    }
}

// round 3
// speedup vs baseline: 1.3013x; 1.3013x over previous
#include <cuda_runtime.h>
#include <math.h>

#define NN 50000
#define NE 800000
#define D  128
#define RB 64
#define NEG 0.2f
#define BNEPS 1e-5f
#define SB 196   // scan blocks (196*256 = 50176 >= NN)

// ---------------- static device scratch (no allocations allowed) ----------------
__device__ float g_xl[NN * D];
__device__ float g_xr[NN * D];
__device__ float g_out[NN * D];
__device__ float g_xbuf[NN * D];
__device__ int   g_srcs[NE];
__device__ int   g_off[NN + 1];
__device__ int   g_cur[NN];
__device__ int   g_cnt[NN];
__device__ int   g_part[256];
__device__ float g_colsum[D];
__device__ float g_colsq[D];
__device__ int   g_is64;

// ---------------- edge dtype probe ----------------
// int64 little-endian values < 2^31 have zero upper words at odd positions.
__global__ void k_detect(const int* __restrict__ w) {
    if (threadIdx.x == 0 && blockIdx.x == 0) {
        int allz = 1;
        for (int i = 1; i < 64; i += 2)
            if (w[i] != 0) allz = 0;
        g_is64 = allz;
    }
}

__device__ __forceinline__ int edge_at(const int* __restrict__ w, int pos, int is64) {
    return is64 ? w[(long long)pos * 2] : w[pos];
}

// ---------------- CSR build ----------------
__global__ void k_zero_cnt() {
    int i = blockIdx.x * 256 + threadIdx.x;
    if (i < NN) g_cnt[i] = 0;
}

__global__ void k_hist(const int* __restrict__ ei) {
    int e = blockIdx.x * 256 + threadIdx.x;
    if (e < NE) {
        int dst = edge_at(ei, NE + e, g_is64);
        atomicAdd(&g_cnt[dst], 1);
    }
}

// stage 1: per-block partial sums of counts
__global__ void k_part() {
    __shared__ int sh[256];
    int tid = threadIdx.x;
    int i = blockIdx.x * 256 + tid;
    int v = (i < NN) ? g_cnt[i] : 0;
    sh[tid] = v;
    __syncthreads();
    for (int o = 128; o > 0; o >>= 1) {
        if (tid < o) sh[tid] += sh[tid + o];
        __syncthreads();
    }
    if (tid == 0) g_part[blockIdx.x] = sh[0];
}

// stage 2: exclusive scan of the SB partials (1 small block)
__global__ void k_scanpart() {
    __shared__ int sh[256];
    int tid = threadIdx.x;
    int v = (tid < SB) ? g_part[tid] : 0;
    sh[tid] = v;
    __syncthreads();
    for (int o = 1; o < 256; o <<= 1) {
        int t = (tid >= o) ? sh[tid - o] : 0;
        __syncthreads();
        sh[tid] += t;
        __syncthreads();
    }
    g_part[tid] = sh[tid] - v;  // exclusive
}

// stage 3: local inclusive scan + block base -> offsets
__global__ void k_off() {
    __shared__ int sh[256];
    int tid = threadIdx.x;
    int i = blockIdx.x * 256 + tid;
    int v = (i < NN) ? g_cnt[i] : 0;
    sh[tid] = v;
    __syncthreads();
    for (int o = 1; o < 256; o <<= 1) {
        int t = (tid >= o) ? sh[tid - o] : 0;
        __syncthreads();
        sh[tid] += t;
        __syncthreads();
    }
    int excl = sh[tid] - v + g_part[blockIdx.x];
    if (i < NN) {
        g_off[i] = excl;
        g_cur[i] = excl;
        if (i == NN - 1) g_off[NN] = excl + v;
    }
}

__global__ void k_scatter(const int* __restrict__ ei) {
    int e = blockIdx.x * 256 + threadIdx.x;
    if (e < NE) {
        int is64 = g_is64;
        int src = edge_at(ei, e, is64);
        int dst = edge_at(ei, NE + e, is64);
        int pos = atomicAdd(&g_cur[dst], 1);
        g_srcs[pos] = src;
    }
}

// ---------------- fused dual GEMM: xl = x@Wl, xr = x@Wr ----------------
__global__ void __launch_bounds__(256, 1)
k_gemm(const float* __restrict__ xin, const float* __restrict__ Wl,
       const float* __restrict__ Wr) {
    extern __shared__ float sm[];
    float* sW = sm;            // [2][128][128]
    float* sX = sm + 32768;    // [RB][128]
    int tid = threadIdx.x;
    const float* xsrc = xin ? xin : g_xbuf;
    {
        float4* d = (float4*)sW;
        const float4* a = (const float4*)Wl;
        const float4* b = (const float4*)Wr;
        for (int i = tid; i < 4096; i += 256) {
            d[i] = a[i];
            d[4096 + i] = b[i];
        }
    }
    int row0 = blockIdx.x * RB;
    {
        float4* d = (float4*)sX;
        for (int i = tid; i < RB * 32; i += 256) {
            int r = i >> 5;
            int row = row0 + r;
            float4 v = (row < NN) ? ((const float4*)xsrc)[row * 32 + (i & 31)]
                                  : make_float4(0.f, 0.f, 0.f, 0.f);
            d[i] = v;
        }
    }
    __syncthreads();

    const float* Ws = sW + ((tid >> 7) << 14);
    int col = tid & 127;
    float acc[RB];
#pragma unroll
    for (int r = 0; r < RB; r++) acc[r] = 0.f;

    for (int kg = 0; kg < 32; kg++) {
        float w0 = Ws[(kg * 4 + 0) * 128 + col];
        float w1 = Ws[(kg * 4 + 1) * 128 + col];
        float w2 = Ws[(kg * 4 + 2) * 128 + col];
        float w3 = Ws[(kg * 4 + 3) * 128 + col];
#pragma unroll
        for (int r = 0; r < RB; r++) {
            float4 xv = *(const float4*)(sX + r * 128 + kg * 4);
            acc[r] = fmaf(xv.x, w0, acc[r]);
            acc[r] = fmaf(xv.y, w1, acc[r]);
            acc[r] = fmaf(xv.z, w2, acc[r]);
            acc[r] = fmaf(xv.w, w3, acc[r]);
        }
    }
    float* outp = (tid < 128) ? g_xl : g_xr;
#pragma unroll
    for (int r = 0; r < RB; r++) {
        int row = row0 + r;
        if (row < NN) outp[row * 128 + col] = acc[r];
    }
}

// ---------------- per-node GATv2: single-pass online softmax + aggregate ----------------
__global__ void k_node(const float* __restrict__ att, const float* __restrict__ bias) {
    int gw = (blockIdx.x * blockDim.x + threadIdx.x) >> 5;
    int lane = threadIdx.x & 31;
    if (gw >= NN) return;
    int beg = g_off[gw], end = g_off[gw + 1];

    const float4 xrv = *(const float4*)(g_xr + gw * 128 + lane * 4);
    const float4 av = *(const float4*)(att + lane * 4);

    float m = -1e30f, sum = 0.f;
    float ax = 0.f, ay = 0.f, az = 0.f, aw = 0.f;

    for (int p = beg; p < end; p++) {
        int s = g_srcs[p];
        float4 v = *(const float4*)(g_xl + s * 128 + lane * 4);
        float t0 = v.x + xrv.x; t0 = t0 > 0.f ? t0 : NEG * t0;
        float t1 = v.y + xrv.y; t1 = t1 > 0.f ? t1 : NEG * t1;
        float t2 = v.z + xrv.z; t2 = t2 > 0.f ? t2 : NEG * t2;
        float t3 = v.w + xrv.w; t3 = t3 > 0.f ? t3 : NEG * t3;
        float d = t0 * av.x + t1 * av.y + t2 * av.z + t3 * av.w;
#pragma unroll
        for (int o = 16; o > 0; o >>= 1) d += __shfl_xor_sync(0xffffffffu, d, o);
        // online softmax update (all lanes hold identical d, m, sum)
        float mn = fmaxf(m, d);
        float c = __expf(m - mn);   // rescale factor (1.0 when no new max)
        float w = __expf(d - mn);
        sum = sum * c + w;
        ax = fmaf(ax, c, w * v.x);
        ay = fmaf(ay, c, w * v.y);
        az = fmaf(az, c, w * v.z);
        aw = fmaf(aw, c, w * v.w);
        m = mn;
    }
    float inv = 1.f / (sum + 1e-16f);
    float4 bv = *(const float4*)(bias + lane * 4);
    float4 o4;
    o4.x = fmaf(ax, inv, bv.x);
    o4.y = fmaf(ay, inv, bv.y);
    o4.z = fmaf(az, inv, bv.z);
    o4.w = fmaf(aw, inv, bv.w);
    *(float4*)(g_out + gw * 128 + lane * 4) = o4;
}

// ---------------- BatchNorm stats + BN->GELU apply ----------------
__global__ void k_zero_cols() {
    g_colsum[threadIdx.x] = 0.f;
    g_colsq[threadIdx.x] = 0.f;
}

// 296 blocks x 256 threads; float4 columns; shared reduce; 256 atomics/block
__global__ void k_bn() {
    int tid = threadIdx.x;
    int c4 = tid & 31;   // float4 column group 0..31
    int rg = tid >> 5;   // row group 0..7
    float4 s = make_float4(0.f, 0.f, 0.f, 0.f);
    float4 q = make_float4(0.f, 0.f, 0.f, 0.f);
    for (int r = blockIdx.x * 8 + rg; r < NN; r += gridDim.x * 8) {
        float4 v = ((const float4*)g_out)[r * 32 + c4];
        s.x += v.x; s.y += v.y; s.z += v.z; s.w += v.w;
        q.x = fmaf(v.x, v.x, q.x); q.y = fmaf(v.y, v.y, q.y);
        q.z = fmaf(v.z, v.z, q.z); q.w = fmaf(v.w, v.w, q.w);
    }
    __shared__ float shs[8][32][4];
    __shared__ float shq[8][32][4];
    shs[rg][c4][0] = s.x; shs[rg][c4][1] = s.y; shs[rg][c4][2] = s.z; shs[rg][c4][3] = s.w;
    shq[rg][c4][0] = q.x; shq[rg][c4][1] = q.y; shq[rg][c4][2] = q.z; shq[rg][c4][3] = q.w;
    __syncthreads();
    if (tid < 128) {  // 128 threads: one per column
        int col = tid;
        int cc4 = col >> 2, ce = col & 3;
        float ts = 0.f, tq = 0.f;
#pragma unroll
        for (int g = 0; g < 8; g++) {
            ts += shs[g][cc4][ce];
            tq += shq[g][cc4][ce];
        }
        atomicAdd(&g_colsum[col], ts);
        atomicAdd(&g_colsq[col], tq);
    }
}

__global__ void k_bnapply(const float* __restrict__ gamma,
                          const float* __restrict__ beta,
                          float* __restrict__ dptr) {
    int i = blockIdx.x * 256 + threadIdx.x;  // over NN*32 float4s
    if (i >= NN * 32) return;
    int c4 = (i & 31) * 4;
    const float invN = 1.f / (float)NN;
    float4 v = ((const float4*)g_out)[i];
    float4 o;
    {
        float mu = g_colsum[c4 + 0] * invN;
        float var = g_colsq[c4 + 0] * invN - mu * mu;
        float y = gamma[c4 + 0] * (v.x - mu) * rsqrtf(var + BNEPS) + beta[c4 + 0];
        o.x = 0.5f * y * (1.f + erff(y * 0.70710678118654752f));
    }
    {
        float mu = g_colsum[c4 + 1] * invN;
        float var = g_colsq[c4 + 1] * invN - mu * mu;
        float y = gamma[c4 + 1] * (v.y - mu) * rsqrtf(var + BNEPS) + beta[c4 + 1];
        o.y = 0.5f * y * (1.f + erff(y * 0.70710678118654752f));
    }
    {
        float mu = g_colsum[c4 + 2] * invN;
        float var = g_colsq[c4 + 2] * invN - mu * mu;
        float y = gamma[c4 + 2] * (v.z - mu) * rsqrtf(var + BNEPS) + beta[c4 + 2];
        o.z = 0.5f * y * (1.f + erff(y * 0.70710678118654752f));
    }
    {
        float mu = g_colsum[c4 + 3] * invN;
        float var = g_colsq[c4 + 3] * invN - mu * mu;
        float y = gamma[c4 + 3] * (v.w - mu) * rsqrtf(var + BNEPS) + beta[c4 + 3];
        o.w = 0.5f * y * (1.f + erff(y * 0.70710678118654752f));
    }
    float* dst = dptr ? dptr : g_xbuf;
    ((float4*)dst)[i] = o;
}

// ---------------- launch ----------------
extern "C" void kernel_launch(void* const* d_in, const int* in_sizes, int n_in,
                              void* d_out, int out_size) {
    const float* x = (const float*)d_in[0];
    const int* ei = (const int*)d_in[1];   // int32 words; int64 handled via probe
    const float* Wl = (const float*)d_in[2];
    const float* Wr = (const float*)d_in[3];
    const float* att = (const float*)d_in[4];
    const float* bias = (const float*)d_in[5];
    const float* gamma = (const float*)d_in[6];
    const float* beta = (const float*)d_in[7];
    float* outp = (float*)d_out;

    cudaFuncSetAttribute(k_gemm, cudaFuncAttributeMaxDynamicSharedMemorySize, 163840);

    // CSR by dst
    k_detect<<<1, 32>>>(ei);
    k_zero_cnt<<<(NN + 255) / 256, 256>>>();
    k_hist<<<(NE + 255) / 256, 256>>>(ei);
    k_part<<<SB, 256>>>();
    k_scanpart<<<1, 256>>>();
    k_off<<<SB, 256>>>();
    k_scatter<<<(NE + 255) / 256, 256>>>(ei);

    const int gemm_blocks = (NN + RB - 1) / RB;
    for (int l = 0; l < 3; l++) {
        const float* xin = (l == 0) ? x : nullptr;  // nullptr -> g_xbuf inside kernel
        k_gemm<<<gemm_blocks, 256, 163840>>>(xin, Wl + l * D * D, Wr + l * D * D);
        k_node<<<(NN + 7) / 8, 256>>>(att + l * D, bias + l * D);
        k_zero_cols<<<1, 128>>>();
        k_bn<<<296, 256>>>();
        float* dst = (l == 2) ? outp : nullptr;  // nullptr -> g_xbuf inside kernel
        k_bnapply<<<(NN * 32 + 255) / 256, 256>>>(gamma + l * D, beta + l * D, dst);
    }
}

// round 5
// speedup vs baseline: 1.6343x; 1.2559x over previous
#include <cuda_runtime.h>
#include <cuda_bf16.h>
#include <math.h>
#include <cstdint>

#define NN 50000
#define NE 800000
#define D  128
#define NEG 0.2f
#define BNEPS 1e-5f
#define SB 196   // scan blocks (196*256 = 50176 >= NN)

// ---------------- static device scratch (no allocations allowed) ----------------
__device__ float g_xl[NN * D];
__device__ float g_xr[NN * D];
__device__ float g_out[NN * D];
__device__ __nv_bfloat16 g_xh[NN * D];
__device__ __nv_bfloat16 g_xlo[NN * D];
__device__ __nv_bfloat16 g_whi[3 * 2 * D * D];   // W^T per layer/matrix: [lm][n][k]
__device__ __nv_bfloat16 g_wlo[3 * 2 * D * D];
__device__ int   g_srcs[NE];
__device__ int   g_off[NN + 1];
__device__ int   g_cur[NN];
__device__ int   g_cnt[NN];
__device__ int   g_part[256];
__device__ float g_colsum[D];
__device__ float g_colsq[D];
__device__ int   g_is64;

// ---------------- edge dtype probe ----------------
__global__ void k_detect(const int* __restrict__ w) {
    if (threadIdx.x == 0 && blockIdx.x == 0) {
        int allz = 1;
        for (int i = 1; i < 64; i += 2)
            if (w[i] != 0) allz = 0;
        g_is64 = allz;
    }
}

__device__ __forceinline__ int edge_at(const int* __restrict__ w, int pos, int is64) {
    return is64 ? w[(long long)pos * 2] : w[pos];
}

// ---------------- CSR build ----------------
__global__ void k_zero_cnt() {
    int i = blockIdx.x * 256 + threadIdx.x;
    if (i < NN) g_cnt[i] = 0;
}

__global__ void k_hist(const int* __restrict__ ei) {
    int e = blockIdx.x * 256 + threadIdx.x;
    if (e < NE) atomicAdd(&g_cnt[edge_at(ei, NE + e, g_is64)], 1);
}

__global__ void k_part() {
    __shared__ int sh[256];
    int tid = threadIdx.x;
    int i = blockIdx.x * 256 + tid;
    int v = (i < NN) ? g_cnt[i] : 0;
    sh[tid] = v;
    __syncthreads();
    for (int o = 128; o > 0; o >>= 1) {
        if (tid < o) sh[tid] += sh[tid + o];
        __syncthreads();
    }
    if (tid == 0) g_part[blockIdx.x] = sh[0];
}

__global__ void k_scanpart() {
    __shared__ int sh[256];
    int tid = threadIdx.x;
    int v = (tid < SB) ? g_part[tid] : 0;
    sh[tid] = v;
    __syncthreads();
    for (int o = 1; o < 256; o <<= 1) {
        int t = (tid >= o) ? sh[tid - o] : 0;
        __syncthreads();
        sh[tid] += t;
        __syncthreads();
    }
    g_part[tid] = sh[tid] - v;
}

__global__ void k_off() {
    __shared__ int sh[256];
    int tid = threadIdx.x;
    int i = blockIdx.x * 256 + tid;
    int v = (i < NN) ? g_cnt[i] : 0;
    sh[tid] = v;
    __syncthreads();
    for (int o = 1; o < 256; o <<= 1) {
        int t = (tid >= o) ? sh[tid - o] : 0;
        __syncthreads();
        sh[tid] += t;
        __syncthreads();
    }
    int excl = sh[tid] - v + g_part[blockIdx.x];
    if (i < NN) {
        g_off[i] = excl;
        g_cur[i] = excl;
        if (i == NN - 1) g_off[NN] = excl + v;
    }
}

__global__ void k_scatter(const int* __restrict__ ei) {
    int e = blockIdx.x * 256 + threadIdx.x;
    if (e < NE) {
        int is64 = g_is64;
        int src = edge_at(ei, e, is64);
        int dst = edge_at(ei, NE + e, is64);
        int pos = atomicAdd(&g_cur[dst], 1);
        g_srcs[pos] = src;
    }
}

// ---------------- conversions (fp32 -> split bf16) ----------------
__device__ __forceinline__ void split2(float a, float b, uint32_t& hi, uint32_t& lo) {
    __nv_bfloat16 ha = __float2bfloat16(a);
    __nv_bfloat16 hb = __float2bfloat16(b);
    __nv_bfloat16 la = __float2bfloat16(a - __bfloat162float(ha));
    __nv_bfloat16 lb = __float2bfloat16(b - __bfloat162float(hb));
    hi = (uint32_t)__bfloat16_as_ushort(ha) | ((uint32_t)__bfloat16_as_ushort(hb) << 16);
    lo = (uint32_t)__bfloat16_as_ushort(la) | ((uint32_t)__bfloat16_as_ushort(lb) << 16);
}

// W^T split: wt[lm][n][k] = W[l][k][n]   (lm = l*2+m; m: 0=Wl, 1=Wr)
__global__ void k_cvt_w(const float* __restrict__ Wl, const float* __restrict__ Wr) {
    int idx = blockIdx.x * 256 + threadIdx.x;
    if (idx >= 3 * 2 * D * D) return;
    int lm = idx >> 14, r = idx & 16383;
    int n = r >> 7, k = r & 127;
    int l = lm >> 1, m = lm & 1;
    const float* W = m ? Wr : Wl;
    float v = W[l * D * D + k * D + n];
    __nv_bfloat16 h = __float2bfloat16(v);
    __nv_bfloat16 lo = __float2bfloat16(v - __bfloat162float(h));
    g_whi[idx] = h;
    g_wlo[idx] = lo;
}

__global__ void k_cvt_x(const float* __restrict__ x) {
    int i = blockIdx.x * 256 + threadIdx.x;  // over NN*64 float2 groups
    if (i >= NN * 64) return;
    float2 v = ((const float2*)x)[i];
    uint32_t hi, lo;
    split2(v.x, v.y, hi, lo);
    ((uint32_t*)g_xh)[i] = hi;
    ((uint32_t*)g_xlo)[i] = lo;
}

// ---------------- tensor-core dual GEMM via mma.sync (baseline PTX) ----------------
// xl = x@Wl, xr = x@Wr, split bf16 3-term: xh*Wh + xh*Wl + xl*Wh
// Block: 256 thr = 8 warps = 2 row-groups x 4 col-groups. Tile 64 rows x 256 cols.
__device__ __forceinline__ void mma16816(float* c, const uint32_t* a, const uint32_t* b) {
    asm volatile(
        "mma.sync.aligned.m16n8k16.row.col.f32.bf16.bf16.f32 "
        "{%0,%1,%2,%3}, {%4,%5,%6,%7}, {%8,%9}, {%0,%1,%2,%3};"
        : "+f"(c[0]), "+f"(c[1]), "+f"(c[2]), "+f"(c[3])
        : "r"(a[0]), "r"(a[1]), "r"(a[2]), "r"(a[3]), "r"(b[0]), "r"(b[1]));
}

__global__ void __launch_bounds__(256, 2) k_gemm_mma(int l) {
    int tid = threadIdx.x, wid = tid >> 5, lane = tid & 31;
    int g = lane >> 2, t = lane & 3;
    int rg = wid >> 2;            // row group 0..1
    int cg = wid & 3;             // col group 0..3
    int m = cg >> 1;              // 0 = xl, 1 = xr
    int colbase = (cg & 1) * 64;
    int row0 = blockIdx.x * 64 + rg * 32;
    const __nv_bfloat16* __restrict__ Bh = g_whi + (l * 2 + m) * D * D;
    const __nv_bfloat16* __restrict__ Bl = g_wlo + (l * 2 + m) * D * D;

    float acc[2][8][4];
#pragma unroll
    for (int mt = 0; mt < 2; mt++)
#pragma unroll
        for (int nt = 0; nt < 8; nt++)
#pragma unroll
            for (int q = 0; q < 4; q++) acc[mt][nt][q] = 0.f;

#pragma unroll
    for (int ks = 0; ks < 8; ks++) {
        int k = ks * 16 + 2 * t;
        uint32_t ah[2][4], al[2][4];
#pragma unroll
        for (int mt = 0; mt < 2; mt++) {
            int r0 = row0 + mt * 16 + g;
            int r1 = r0 + 8;
            bool v0 = r0 < NN, v1 = r1 < NN;
            ah[mt][0] = v0 ? *(const uint32_t*)(g_xh + r0 * D + k) : 0u;
            ah[mt][1] = v1 ? *(const uint32_t*)(g_xh + r1 * D + k) : 0u;
            ah[mt][2] = v0 ? *(const uint32_t*)(g_xh + r0 * D + k + 8) : 0u;
            ah[mt][3] = v1 ? *(const uint32_t*)(g_xh + r1 * D + k + 8) : 0u;
            al[mt][0] = v0 ? *(const uint32_t*)(g_xlo + r0 * D + k) : 0u;
            al[mt][1] = v1 ? *(const uint32_t*)(g_xlo + r1 * D + k) : 0u;
            al[mt][2] = v0 ? *(const uint32_t*)(g_xlo + r0 * D + k + 8) : 0u;
            al[mt][3] = v1 ? *(const uint32_t*)(g_xlo + r1 * D + k + 8) : 0u;
        }
#pragma unroll
        for (int nt = 0; nt < 8; nt++) {
            int n = colbase + nt * 8 + g;
            uint32_t bh[2], bl[2];
            bh[0] = *(const uint32_t*)(Bh + n * D + k);
            bh[1] = *(const uint32_t*)(Bh + n * D + k + 8);
            bl[0] = *(const uint32_t*)(Bl + n * D + k);
            bl[1] = *(const uint32_t*)(Bl + n * D + k + 8);
#pragma unroll
            for (int mt = 0; mt < 2; mt++) {
                mma16816(acc[mt][nt], ah[mt], bh);
                mma16816(acc[mt][nt], ah[mt], bl);
                mma16816(acc[mt][nt], al[mt], bh);
            }
        }
    }

    float* dst = m ? g_xr : g_xl;
#pragma unroll
    for (int mt = 0; mt < 2; mt++) {
#pragma unroll
        for (int nt = 0; nt < 8; nt++) {
            int r0 = row0 + mt * 16 + g;
            int c = colbase + nt * 8 + 2 * t;
            if (r0 < NN)
                *(float2*)(dst + r0 * D + c) = make_float2(acc[mt][nt][0], acc[mt][nt][1]);
            if (r0 + 8 < NN)
                *(float2*)(dst + (r0 + 8) * D + c) = make_float2(acc[mt][nt][2], acc[mt][nt][3]);
        }
    }
}

// ---------------- per-node GATv2: single-pass online softmax + aggregate ----------------
__global__ void k_node(const float* __restrict__ att, const float* __restrict__ bias) {
    int gw = (blockIdx.x * blockDim.x + threadIdx.x) >> 5;
    int lane = threadIdx.x & 31;
    if (gw >= NN) return;
    int beg = g_off[gw], end = g_off[gw + 1];

    const float4 xrv = *(const float4*)(g_xr + gw * 128 + lane * 4);
    const float4 av = *(const float4*)(att + lane * 4);

    float m = -1e30f, sum = 0.f;
    float ax = 0.f, ay = 0.f, az = 0.f, aw = 0.f;

    for (int p = beg; p < end; p++) {
        int s = g_srcs[p];
        float4 v = *(const float4*)(g_xl + s * 128 + lane * 4);
        float t0 = v.x + xrv.x; t0 = t0 > 0.f ? t0 : NEG * t0;
        float t1 = v.y + xrv.y; t1 = t1 > 0.f ? t1 : NEG * t1;
        float t2 = v.z + xrv.z; t2 = t2 > 0.f ? t2 : NEG * t2;
        float t3 = v.w + xrv.w; t3 = t3 > 0.f ? t3 : NEG * t3;
        float d = t0 * av.x + t1 * av.y + t2 * av.z + t3 * av.w;
#pragma unroll
        for (int o = 16; o > 0; o >>= 1) d += __shfl_xor_sync(0xffffffffu, d, o);
        float mn = fmaxf(m, d);
        float c = __expf(m - mn);
        float w = __expf(d - mn);
        sum = sum * c + w;
        ax = fmaf(ax, c, w * v.x);
        ay = fmaf(ay, c, w * v.y);
        az = fmaf(az, c, w * v.z);
        aw = fmaf(aw, c, w * v.w);
        m = mn;
    }
    float inv = 1.f / (sum + 1e-16f);
    float4 bv = *(const float4*)(bias + lane * 4);
    float4 o4;
    o4.x = fmaf(ax, inv, bv.x);
    o4.y = fmaf(ay, inv, bv.y);
    o4.z = fmaf(az, inv, bv.z);
    o4.w = fmaf(aw, inv, bv.w);
    *(float4*)(g_out + gw * 128 + lane * 4) = o4;
}

// ---------------- BatchNorm stats + BN->GELU apply ----------------
__global__ void k_zero_cols() {
    g_colsum[threadIdx.x] = 0.f;
    g_colsq[threadIdx.x] = 0.f;
}

__global__ void k_bn() {
    int tid = threadIdx.x;
    int c4 = tid & 31;
    int rg = tid >> 5;
    float4 s = make_float4(0.f, 0.f, 0.f, 0.f);
    float4 q = make_float4(0.f, 0.f, 0.f, 0.f);
    for (int r = blockIdx.x * 8 + rg; r < NN; r += gridDim.x * 8) {
        float4 v = ((const float4*)g_out)[r * 32 + c4];
        s.x += v.x; s.y += v.y; s.z += v.z; s.w += v.w;
        q.x = fmaf(v.x, v.x, q.x); q.y = fmaf(v.y, v.y, q.y);
        q.z = fmaf(v.z, v.z, q.z); q.w = fmaf(v.w, v.w, q.w);
    }
    __shared__ float shs[8][32][4];
    __shared__ float shq[8][32][4];
    shs[rg][c4][0] = s.x; shs[rg][c4][1] = s.y; shs[rg][c4][2] = s.z; shs[rg][c4][3] = s.w;
    shq[rg][c4][0] = q.x; shq[rg][c4][1] = q.y; shq[rg][c4][2] = q.z; shq[rg][c4][3] = q.w;
    __syncthreads();
    if (tid < 128) {
        int col = tid;
        int cc4 = col >> 2, ce = col & 3;
        float ts = 0.f, tq = 0.f;
#pragma unroll
        for (int g = 0; g < 8; g++) {
            ts += shs[g][cc4][ce];
            tq += shq[g][cc4][ce];
        }
        atomicAdd(&g_colsum[col], ts);
        atomicAdd(&g_colsq[col], tq);
    }
}

// BN + erf-GELU; final layer -> fp32 d_out, else -> split bf16 for next GEMM
__global__ void k_bnapply(const float* __restrict__ gamma,
                          const float* __restrict__ beta,
                          float* __restrict__ dptr) {
    int i = blockIdx.x * 256 + threadIdx.x;  // over NN*32 float4s
    if (i >= NN * 32) return;
    int c4 = (i & 31) * 4;
    const float invN = 1.f / (float)NN;
    float4 v = ((const float4*)g_out)[i];
    float o[4];
    float vin[4] = {v.x, v.y, v.z, v.w};
#pragma unroll
    for (int c = 0; c < 4; c++) {
        float mu = g_colsum[c4 + c] * invN;
        float var = g_colsq[c4 + c] * invN - mu * mu;
        float y = gamma[c4 + c] * (vin[c] - mu) * rsqrtf(var + BNEPS) + beta[c4 + c];
        o[c] = 0.5f * y * (1.f + erff(y * 0.70710678118654752f));
    }
    if (dptr) {
        ((float4*)dptr)[i] = make_float4(o[0], o[1], o[2], o[3]);
    } else {
        uint32_t h0, l0, h1, l1;
        split2(o[0], o[1], h0, l0);
        split2(o[2], o[3], h1, l1);
        ((uint2*)g_xh)[i] = make_uint2(h0, h1);
        ((uint2*)g_xlo)[i] = make_uint2(l0, l1);
    }
}

// ---------------- launch ----------------
extern "C" void kernel_launch(void* const* d_in, const int* in_sizes, int n_in,
                              void* d_out, int out_size) {
    const float* x = (const float*)d_in[0];
    const int* ei = (const int*)d_in[1];
    const float* Wl = (const float*)d_in[2];
    const float* Wr = (const float*)d_in[3];
    const float* att = (const float*)d_in[4];
    const float* bias = (const float*)d_in[5];
    const float* gamma = (const float*)d_in[6];
    const float* beta = (const float*)d_in[7];
    float* outp = (float*)d_out;

    // CSR by dst
    k_detect<<<1, 32>>>(ei);
    k_zero_cnt<<<(NN + 255) / 256, 256>>>();
    k_hist<<<(NE + 255) / 256, 256>>>(ei);
    k_part<<<SB, 256>>>();
    k_scanpart<<<1, 256>>>();
    k_off<<<SB, 256>>>();
    k_scatter<<<(NE + 255) / 256, 256>>>(ei);

    // weight + input conversion to split bf16
    k_cvt_w<<<(3 * 2 * D * D + 255) / 256, 256>>>(Wl, Wr);
    k_cvt_x<<<(NN * 64 + 255) / 256, 256>>>(x);

    const int gemm_blocks = (NN + 63) / 64;
    for (int l = 0; l < 3; l++) {
        k_gemm_mma<<<gemm_blocks, 256>>>(l);
        k_node<<<(NN + 7) / 8, 256>>>(att + l * D, bias + l * D);
        k_zero_cols<<<1, 128>>>();
        k_bn<<<296, 256>>>();
        float* dst = (l == 2) ? outp : nullptr;
        k_bnapply<<<(NN * 32 + 255) / 256, 256>>>(gamma + l * D, beta + l * D, dst);
    }
}

// round 7
// speedup vs baseline: 1.7508x; 1.0713x over previous
#include <cuda_runtime.h>
#include <cuda_bf16.h>
#include <math.h>
#include <cstdint>

#define NN 50000
#define NE 800000
#define D  128
#define NEG 0.2f
#define BNEPS 1e-5f
#define SB 196   // scan blocks (196*256 = 50176 >= NN)

// ---------------- static device scratch (no allocations allowed) ----------------
__device__ float g_xl[NN * D];
__device__ float g_xr[NN * D];
__device__ float g_out[NN * D];
__device__ __nv_bfloat16 g_xh[NN * D];
__device__ __nv_bfloat16 g_xlo[NN * D];
__device__ __nv_bfloat16 g_whi[3 * 2 * D * D];   // W^T per layer/matrix: [lm][n][k]
__device__ __nv_bfloat16 g_wlo[3 * 2 * D * D];
__device__ int   g_srcs[NE];
__device__ int   g_off[NN + 1];
__device__ int   g_cur[NN];
__device__ int   g_cnt[NN];
__device__ int   g_part[256];
__device__ float g_colsum[D];
__device__ float g_colsq[D];
__device__ int   g_is64;

// ---------------- edge dtype probe + counter zero (fused) ----------------
__global__ void k_detect_zero(const int* __restrict__ w) {
    int i = blockIdx.x * 256 + threadIdx.x;
    if (i < NN) g_cnt[i] = 0;
    if (i == 0) {
        int allz = 1;
        for (int j = 1; j < 64; j += 2)
            if (w[j] != 0) allz = 0;
        g_is64 = allz;
    }
}

__device__ __forceinline__ int edge_at(const int* __restrict__ w, int pos, int is64) {
    return is64 ? w[(long long)pos * 2] : w[pos];
}

// ---------------- CSR build ----------------
__global__ void k_hist(const int* __restrict__ ei) {
    int e = blockIdx.x * 256 + threadIdx.x;
    if (e < NE) atomicAdd(&g_cnt[edge_at(ei, NE + e, g_is64)], 1);
}

__global__ void k_part() {
    __shared__ int sh[256];
    int tid = threadIdx.x;
    int i = blockIdx.x * 256 + tid;
    int v = (i < NN) ? g_cnt[i] : 0;
    sh[tid] = v;
    __syncthreads();
    for (int o = 128; o > 0; o >>= 1) {
        if (tid < o) sh[tid] += sh[tid + o];
        __syncthreads();
    }
    if (tid == 0) g_part[blockIdx.x] = sh[0];
}

__global__ void k_scanpart() {
    __shared__ int sh[256];
    int tid = threadIdx.x;
    int v = (tid < SB) ? g_part[tid] : 0;
    sh[tid] = v;
    __syncthreads();
    for (int o = 1; o < 256; o <<= 1) {
        int t = (tid >= o) ? sh[tid - o] : 0;
        __syncthreads();
        sh[tid] += t;
        __syncthreads();
    }
    g_part[tid] = sh[tid] - v;
}

__global__ void k_off() {
    __shared__ int sh[256];
    int tid = threadIdx.x;
    int i = blockIdx.x * 256 + tid;
    int v = (i < NN) ? g_cnt[i] : 0;
    sh[tid] = v;
    __syncthreads();
    for (int o = 1; o < 256; o <<= 1) {
        int t = (tid >= o) ? sh[tid - o] : 0;
        __syncthreads();
        sh[tid] += t;
        __syncthreads();
    }
    int excl = sh[tid] - v + g_part[blockIdx.x];
    if (i < NN) {
        g_off[i] = excl;
        g_cur[i] = excl;
        if (i == NN - 1) g_off[NN] = excl + v;
    }
}

__global__ void k_scatter(const int* __restrict__ ei) {
    int e = blockIdx.x * 256 + threadIdx.x;
    if (e < NE) {
        int is64 = g_is64;
        int src = edge_at(ei, e, is64);
        int dst = edge_at(ei, NE + e, is64);
        int pos = atomicAdd(&g_cur[dst], 1);
        g_srcs[pos] = src;
    }
}

// ---------------- conversions (fp32 -> split bf16) ----------------
__device__ __forceinline__ void split2(float a, float b, uint32_t& hi, uint32_t& lo) {
    __nv_bfloat16 ha = __float2bfloat16(a);
    __nv_bfloat16 hb = __float2bfloat16(b);
    __nv_bfloat16 la = __float2bfloat16(a - __bfloat162float(ha));
    __nv_bfloat16 lb = __float2bfloat16(b - __bfloat162float(hb));
    hi = (uint32_t)__bfloat16_as_ushort(ha) | ((uint32_t)__bfloat16_as_ushort(hb) << 16);
    lo = (uint32_t)__bfloat16_as_ushort(la) | ((uint32_t)__bfloat16_as_ushort(lb) << 16);
}

// W^T split: wt[lm][n][k] = W[l][k][n]   (lm = l*2+m; m: 0=Wl, 1=Wr)
__global__ void k_cvt_w(const float* __restrict__ Wl, const float* __restrict__ Wr) {
    int idx = blockIdx.x * 256 + threadIdx.x;
    if (idx >= 3 * 2 * D * D) return;
    int lm = idx >> 14, r = idx & 16383;
    int n = r >> 7, k = r & 127;
    int l = lm >> 1, m = lm & 1;
    const float* W = m ? Wr : Wl;
    float v = W[l * D * D + k * D + n];
    __nv_bfloat16 h = __float2bfloat16(v);
    __nv_bfloat16 lo = __float2bfloat16(v - __bfloat162float(h));
    g_whi[idx] = h;
    g_wlo[idx] = lo;
}

__global__ void k_cvt_x(const float* __restrict__ x) {
    int i = blockIdx.x * 256 + threadIdx.x;  // over NN*64 float2 groups
    if (i >= NN * 64) return;
    float2 v = ((const float2*)x)[i];
    uint32_t hi, lo;
    split2(v.x, v.y, hi, lo);
    ((uint32_t*)g_xh)[i] = hi;
    ((uint32_t*)g_xlo)[i] = lo;
}

// ---------------- tensor-core dual GEMM via mma.sync (baseline PTX) ----------------
__device__ __forceinline__ void mma16816(float* c, const uint32_t* a, const uint32_t* b) {
    asm volatile(
        "mma.sync.aligned.m16n8k16.row.col.f32.bf16.bf16.f32 "
        "{%0,%1,%2,%3}, {%4,%5,%6,%7}, {%8,%9}, {%0,%1,%2,%3};"
        : "+f"(c[0]), "+f"(c[1]), "+f"(c[2]), "+f"(c[3])
        : "r"(a[0]), "r"(a[1]), "r"(a[2]), "r"(a[3]), "r"(b[0]), "r"(b[1]));
}

__global__ void __launch_bounds__(256, 2) k_gemm_mma(int l) {
    int tid = threadIdx.x, wid = tid >> 5, lane = tid & 31;
    int g = lane >> 2, t = lane & 3;
    int rg = wid >> 2;            // row group 0..1
    int cg = wid & 3;             // col group 0..3
    int m = cg >> 1;              // 0 = xl, 1 = xr
    int colbase = (cg & 1) * 64;
    int row0 = blockIdx.x * 64 + rg * 32;
    const __nv_bfloat16* __restrict__ Bh = g_whi + (l * 2 + m) * D * D;
    const __nv_bfloat16* __restrict__ Bl = g_wlo + (l * 2 + m) * D * D;

    float acc[2][8][4];
#pragma unroll
    for (int mt = 0; mt < 2; mt++)
#pragma unroll
        for (int nt = 0; nt < 8; nt++)
#pragma unroll
            for (int q = 0; q < 4; q++) acc[mt][nt][q] = 0.f;

#pragma unroll
    for (int ks = 0; ks < 8; ks++) {
        int k = ks * 16 + 2 * t;
        uint32_t ah[2][4], al[2][4];
#pragma unroll
        for (int mt = 0; mt < 2; mt++) {
            int r0 = row0 + mt * 16 + g;
            int r1 = r0 + 8;
            bool v0 = r0 < NN, v1 = r1 < NN;
            ah[mt][0] = v0 ? *(const uint32_t*)(g_xh + r0 * D + k) : 0u;
            ah[mt][1] = v1 ? *(const uint32_t*)(g_xh + r1 * D + k) : 0u;
            ah[mt][2] = v0 ? *(const uint32_t*)(g_xh + r0 * D + k + 8) : 0u;
            ah[mt][3] = v1 ? *(const uint32_t*)(g_xh + r1 * D + k + 8) : 0u;
            al[mt][0] = v0 ? *(const uint32_t*)(g_xlo + r0 * D + k) : 0u;
            al[mt][1] = v1 ? *(const uint32_t*)(g_xlo + r1 * D + k) : 0u;
            al[mt][2] = v0 ? *(const uint32_t*)(g_xlo + r0 * D + k + 8) : 0u;
            al[mt][3] = v1 ? *(const uint32_t*)(g_xlo + r1 * D + k + 8) : 0u;
        }
#pragma unroll
        for (int nt = 0; nt < 8; nt++) {
            int n = colbase + nt * 8 + g;
            uint32_t bh[2], bl[2];
            bh[0] = *(const uint32_t*)(Bh + n * D + k);
            bh[1] = *(const uint32_t*)(Bh + n * D + k + 8);
            bl[0] = *(const uint32_t*)(Bl + n * D + k);
            bl[1] = *(const uint32_t*)(Bl + n * D + k + 8);
#pragma unroll
            for (int mt = 0; mt < 2; mt++) {
                mma16816(acc[mt][nt], ah[mt], bh);
                mma16816(acc[mt][nt], ah[mt], bl);
                mma16816(acc[mt][nt], al[mt], bh);
            }
        }
    }

    float* dst = m ? g_xr : g_xl;
#pragma unroll
    for (int mt = 0; mt < 2; mt++) {
#pragma unroll
        for (int nt = 0; nt < 8; nt++) {
            int r0 = row0 + mt * 16 + g;
            int c = colbase + nt * 8 + 2 * t;
            if (r0 < NN)
                *(float2*)(dst + r0 * D + c) = make_float2(acc[mt][nt][0], acc[mt][nt][1]);
            if (r0 + 8 < NN)
                *(float2*)(dst + (r0 + 8) * D + c) = make_float2(acc[mt][nt][2], acc[mt][nt][3]);
        }
    }
}

// ---------------- per-node GATv2: 16-lane groups, 2 edges in flight ----------------
__device__ __forceinline__ float lrelu(float z) {
    return z > 0.f ? z : NEG * z;
}

__global__ void __launch_bounds__(64) k_node(const float* __restrict__ att,
                                             const float* __restrict__ bias) {
    int node = blockIdx.x * 2 + (threadIdx.x >> 5);
    if (node >= NN) return;
    int lane = threadIdx.x & 31;
    int l16 = lane & 15;    // 8 channels per lane: [l16*8, l16*8+8)
    int grp = lane >> 4;    // group 0/1: edges beg+grp, beg+grp+2, ...
    // group-local shuffle mask: the two 16-lane groups have different loop
    // trip counts (odd degree), so intra-group shuffles must not name lanes
    // of the other group.
    const unsigned gmask = 0xFFFFu << (grp << 4);
    int beg = g_off[node], end = g_off[node + 1];

    const float4* xr4 = (const float4*)(g_xr + node * 128 + l16 * 8);
    float4 xr0 = xr4[0], xr1 = xr4[1];
    const float4* at4 = (const float4*)(att + l16 * 8);
    float4 a0 = at4[0], a1 = at4[1];

    float m = -1e30f, sum = 0.f;
    float4 acc0 = make_float4(0.f, 0.f, 0.f, 0.f);
    float4 acc1 = make_float4(0.f, 0.f, 0.f, 0.f);

    for (int p = beg + grp; p < end; p += 2) {
        int s = g_srcs[p];
        const float4* v4 = (const float4*)(g_xl + s * 128 + l16 * 8);
        float4 v0 = v4[0], v1 = v4[1];
        float d = lrelu(v0.x + xr0.x) * a0.x;
        d = fmaf(lrelu(v0.y + xr0.y), a0.y, d);
        d = fmaf(lrelu(v0.z + xr0.z), a0.z, d);
        d = fmaf(lrelu(v0.w + xr0.w), a0.w, d);
        d = fmaf(lrelu(v1.x + xr1.x), a1.x, d);
        d = fmaf(lrelu(v1.y + xr1.y), a1.y, d);
        d = fmaf(lrelu(v1.z + xr1.z), a1.z, d);
        d = fmaf(lrelu(v1.w + xr1.w), a1.w, d);
        // reduce across the 16-lane group (xor 1,2,4,8 stays within group)
#pragma unroll
        for (int o = 1; o < 16; o <<= 1) d += __shfl_xor_sync(gmask, d, o);
        // online softmax update (per group)
        float mn = fmaxf(m, d);
        float c = __expf(m - mn);
        float w = __expf(d - mn);
        sum = sum * c + w;
        acc0.x = fmaf(acc0.x, c, w * v0.x);
        acc0.y = fmaf(acc0.y, c, w * v0.y);
        acc0.z = fmaf(acc0.z, c, w * v0.z);
        acc0.w = fmaf(acc0.w, c, w * v0.w);
        acc1.x = fmaf(acc1.x, c, w * v1.x);
        acc1.y = fmaf(acc1.y, c, w * v1.y);
        acc1.z = fmaf(acc1.z, c, w * v1.z);
        acc1.w = fmaf(acc1.w, c, w * v1.w);
        m = mn;
    }
    // both groups done; reconverge, then merge groups (xor 16)
    __syncwarp();
    float mo = __shfl_xor_sync(0xffffffffu, m, 16);
    float so = __shfl_xor_sync(0xffffffffu, sum, 16);
    float ms = fmaxf(m, mo);
    float cme = __expf(m - ms);
    float sum_t = fmaf(so, __expf(mo - ms), sum * cme);
    acc0.x *= cme; acc0.y *= cme; acc0.z *= cme; acc0.w *= cme;
    acc1.x *= cme; acc1.y *= cme; acc1.z *= cme; acc1.w *= cme;
    acc0.x += __shfl_xor_sync(0xffffffffu, acc0.x, 16);
    acc0.y += __shfl_xor_sync(0xffffffffu, acc0.y, 16);
    acc0.z += __shfl_xor_sync(0xffffffffu, acc0.z, 16);
    acc0.w += __shfl_xor_sync(0xffffffffu, acc0.w, 16);
    acc1.x += __shfl_xor_sync(0xffffffffu, acc1.x, 16);
    acc1.y += __shfl_xor_sync(0xffffffffu, acc1.y, 16);
    acc1.z += __shfl_xor_sync(0xffffffffu, acc1.z, 16);
    acc1.w += __shfl_xor_sync(0xffffffffu, acc1.w, 16);
    if (grp == 0) {
        float inv = 1.f / (sum_t + 1e-16f);
        const float4* b4 = (const float4*)(bias + l16 * 8);
        float4 b0 = b4[0], b1 = b4[1];
        float4 o0, o1;
        o0.x = fmaf(acc0.x, inv, b0.x);
        o0.y = fmaf(acc0.y, inv, b0.y);
        o0.z = fmaf(acc0.z, inv, b0.z);
        o0.w = fmaf(acc0.w, inv, b0.w);
        o1.x = fmaf(acc1.x, inv, b1.x);
        o1.y = fmaf(acc1.y, inv, b1.y);
        o1.z = fmaf(acc1.z, inv, b1.z);
        o1.w = fmaf(acc1.w, inv, b1.w);
        float4* op = (float4*)(g_out + node * 128 + l16 * 8);
        op[0] = o0;
        op[1] = o1;
    }
}

// ---------------- BatchNorm stats + BN->GELU apply ----------------
__global__ void k_zero_cols() {
    g_colsum[threadIdx.x] = 0.f;
    g_colsq[threadIdx.x] = 0.f;
}

__global__ void k_bn() {
    int tid = threadIdx.x;
    int c4 = tid & 31;
    int rg = tid >> 5;
    float4 s = make_float4(0.f, 0.f, 0.f, 0.f);
    float4 q = make_float4(0.f, 0.f, 0.f, 0.f);
    for (int r = blockIdx.x * 8 + rg; r < NN; r += gridDim.x * 8) {
        float4 v = ((const float4*)g_out)[r * 32 + c4];
        s.x += v.x; s.y += v.y; s.z += v.z; s.w += v.w;
        q.x = fmaf(v.x, v.x, q.x); q.y = fmaf(v.y, v.y, q.y);
        q.z = fmaf(v.z, v.z, q.z); q.w = fmaf(v.w, v.w, q.w);
    }
    __shared__ float shs[8][32][4];
    __shared__ float shq[8][32][4];
    shs[rg][c4][0] = s.x; shs[rg][c4][1] = s.y; shs[rg][c4][2] = s.z; shs[rg][c4][3] = s.w;
    shq[rg][c4][0] = q.x; shq[rg][c4][1] = q.y; shq[rg][c4][2] = q.z; shq[rg][c4][3] = q.w;
    __syncthreads();
    if (tid < 128) {
        int col = tid;
        int cc4 = col >> 2, ce = col & 3;
        float ts = 0.f, tq = 0.f;
#pragma unroll
        for (int g = 0; g < 8; g++) {
            ts += shs[g][cc4][ce];
            tq += shq[g][cc4][ce];
        }
        atomicAdd(&g_colsum[col], ts);
        atomicAdd(&g_colsq[col], tq);
    }
}

// BN + erf-GELU; final layer -> fp32 d_out, else -> split bf16 for next GEMM
__global__ void k_bnapply(const float* __restrict__ gamma,
                          const float* __restrict__ beta,
                          float* __restrict__ dptr) {
    int i = blockIdx.x * 256 + threadIdx.x;  // over NN*32 float4s
    if (i >= NN * 32) return;
    int c4 = (i & 31) * 4;
    const float invN = 1.f / (float)NN;
    float4 v = ((const float4*)g_out)[i];
    float o[4];
    float vin[4] = {v.x, v.y, v.z, v.w};
#pragma unroll
    for (int c = 0; c < 4; c++) {
        float mu = g_colsum[c4 + c] * invN;
        float var = g_colsq[c4 + c] * invN - mu * mu;
        float y = gamma[c4 + c] * (vin[c] - mu) * rsqrtf(var + BNEPS) + beta[c4 + c];
        o[c] = 0.5f * y * (1.f + erff(y * 0.70710678118654752f));
    }
    if (dptr) {
        ((float4*)dptr)[i] = make_float4(o[0], o[1], o[2], o[3]);
    } else {
        uint32_t h0, l0, h1, l1;
        split2(o[0], o[1], h0, l0);
        split2(o[2], o[3], h1, l1);
        ((uint2*)g_xh)[i] = make_uint2(h0, h1);
        ((uint2*)g_xlo)[i] = make_uint2(l0, l1);
    }
}

// ---------------- launch ----------------
extern "C" void kernel_launch(void* const* d_in, const int* in_sizes, int n_in,
                              void* d_out, int out_size) {
    const float* x = (const float*)d_in[0];
    const int* ei = (const int*)d_in[1];
    const float* Wl = (const float*)d_in[2];
    const float* Wr = (const float*)d_in[3];
    const float* att = (const float*)d_in[4];
    const float* bias = (const float*)d_in[5];
    const float* gamma = (const float*)d_in[6];
    const float* beta = (const float*)d_in[7];
    float* outp = (float*)d_out;

    const int gemm_blocks = (NN + 63) / 64;

    // launches 1-2: conversions; 3: detect+zero; 4: layer-0 GEMM (profiled slot)
    k_cvt_w<<<(3 * 2 * D * D + 255) / 256, 256>>>(Wl, Wr);
    k_cvt_x<<<(NN * 64 + 255) / 256, 256>>>(x);
    k_detect_zero<<<SB, 256>>>(ei);
    k_gemm_mma<<<gemm_blocks, 256>>>(0);

    // CSR by dst
    k_hist<<<(NE + 255) / 256, 256>>>(ei);
    k_part<<<SB, 256>>>();
    k_scanpart<<<1, 256>>>();
    k_off<<<SB, 256>>>();
    k_scatter<<<(NE + 255) / 256, 256>>>(ei);

    for (int l = 0; l < 3; l++) {
        if (l > 0) k_gemm_mma<<<gemm_blocks, 256>>>(l);
        k_node<<<(NN + 1) / 2, 64>>>(att + l * D, bias + l * D);
        k_zero_cols<<<1, 128>>>();
        k_bn<<<296, 256>>>();
        float* dst = (l == 2) ? outp : nullptr;
        k_bnapply<<<(NN * 32 + 255) / 256, 256>>>(gamma + l * D, beta + l * D, dst);
    }
}

// round 8
// speedup vs baseline: 2.4287x; 1.3872x over previous
#include <cuda_runtime.h>
#include <cuda_bf16.h>
#include <math.h>
#include <cstdint>

#define NN 50000
#define NE 800000
#define D  128
#define NEG 0.2f
#define BNEPS 1e-5f
#define SB 196   // scan blocks (196*256 = 50176 >= NN)

// ---------------- static device scratch (no allocations allowed) ----------------
__device__ float g_xl[NN * D];
__device__ float g_xr[NN * D];
__device__ float g_out[NN * D];
__device__ __nv_bfloat16 g_xh[NN * D];
__device__ __nv_bfloat16 g_xlo[NN * D];
__device__ __nv_bfloat16 g_whi[3 * 2 * D * D];   // W^T per layer/matrix: [lm][n][k]
__device__ __nv_bfloat16 g_wlo[3 * 2 * D * D];
__device__ int   g_srcs[NE];
__device__ int   g_off[NN + 1];
__device__ int   g_cur[NN];
__device__ int   g_cnt[NN];
__device__ int   g_part[256];
__device__ float g_colsum[D];
__device__ float g_colsq[D];
__device__ int   g_is64;

// ---------------- edge dtype probe + counter zero (fused) ----------------
__global__ void k_detect_zero(const int* __restrict__ w) {
    int i = blockIdx.x * 256 + threadIdx.x;
    if (i < NN) g_cnt[i] = 0;
    if (i == 0) {
        int allz = 1;
        for (int j = 1; j < 64; j += 2)
            if (w[j] != 0) allz = 0;
        g_is64 = allz;
    }
}

__device__ __forceinline__ int edge_at(const int* __restrict__ w, int pos, int is64) {
    return is64 ? w[(long long)pos * 2] : w[pos];
}

// ---------------- CSR build ----------------
__global__ void k_hist(const int* __restrict__ ei) {
    int e = blockIdx.x * 256 + threadIdx.x;
    if (e < NE) atomicAdd(&g_cnt[edge_at(ei, NE + e, g_is64)], 1);
}

__global__ void k_part() {
    __shared__ int sh[256];
    int tid = threadIdx.x;
    int i = blockIdx.x * 256 + tid;
    int v = (i < NN) ? g_cnt[i] : 0;
    sh[tid] = v;
    __syncthreads();
    for (int o = 128; o > 0; o >>= 1) {
        if (tid < o) sh[tid] += sh[tid + o];
        __syncthreads();
    }
    if (tid == 0) g_part[blockIdx.x] = sh[0];
}

__global__ void k_scanpart() {
    __shared__ int sh[256];
    int tid = threadIdx.x;
    int v = (tid < SB) ? g_part[tid] : 0;
    sh[tid] = v;
    __syncthreads();
    for (int o = 1; o < 256; o <<= 1) {
        int t = (tid >= o) ? sh[tid - o] : 0;
        __syncthreads();
        sh[tid] += t;
        __syncthreads();
    }
    g_part[tid] = sh[tid] - v;
}

__global__ void k_off() {
    __shared__ int sh[256];
    int tid = threadIdx.x;
    int i = blockIdx.x * 256 + tid;
    int v = (i < NN) ? g_cnt[i] : 0;
    sh[tid] = v;
    __syncthreads();
    for (int o = 1; o < 256; o <<= 1) {
        int t = (tid >= o) ? sh[tid - o] : 0;
        __syncthreads();
        sh[tid] += t;
        __syncthreads();
    }
    int excl = sh[tid] - v + g_part[blockIdx.x];
    if (i < NN) {
        g_off[i] = excl;
        g_cur[i] = excl;
        if (i == NN - 1) g_off[NN] = excl + v;
    }
}

__global__ void k_scatter(const int* __restrict__ ei) {
    int e = blockIdx.x * 256 + threadIdx.x;
    if (e < NE) {
        int is64 = g_is64;
        int src = edge_at(ei, e, is64);
        int dst = edge_at(ei, NE + e, is64);
        int pos = atomicAdd(&g_cur[dst], 1);
        g_srcs[pos] = src;
    }
}

// ---------------- conversions (fp32 -> split bf16) ----------------
__device__ __forceinline__ void split2(float a, float b, uint32_t& hi, uint32_t& lo) {
    __nv_bfloat16 ha = __float2bfloat16(a);
    __nv_bfloat16 hb = __float2bfloat16(b);
    __nv_bfloat16 la = __float2bfloat16(a - __bfloat162float(ha));
    __nv_bfloat16 lb = __float2bfloat16(b - __bfloat162float(hb));
    hi = (uint32_t)__bfloat16_as_ushort(ha) | ((uint32_t)__bfloat16_as_ushort(hb) << 16);
    lo = (uint32_t)__bfloat16_as_ushort(la) | ((uint32_t)__bfloat16_as_ushort(lb) << 16);
}

// W^T split: wt[lm][n][k] = W[l][k][n]   (lm = l*2+m; m: 0=Wl, 1=Wr)
__global__ void k_cvt_w(const float* __restrict__ Wl, const float* __restrict__ Wr) {
    int idx = blockIdx.x * 256 + threadIdx.x;
    if (idx >= 3 * 2 * D * D) return;
    int lm = idx >> 14, r = idx & 16383;
    int n = r >> 7, k = r & 127;
    int l = lm >> 1, m = lm & 1;
    const float* W = m ? Wr : Wl;
    float v = W[l * D * D + k * D + n];
    __nv_bfloat16 h = __float2bfloat16(v);
    __nv_bfloat16 lo = __float2bfloat16(v - __bfloat162float(h));
    g_whi[idx] = h;
    g_wlo[idx] = lo;
}

__global__ void k_cvt_x(const float* __restrict__ x) {
    int i = blockIdx.x * 256 + threadIdx.x;  // over NN*64 float2 groups
    if (i >= NN * 64) return;
    float2 v = ((const float2*)x)[i];
    uint32_t hi, lo;
    split2(v.x, v.y, hi, lo);
    ((uint32_t*)g_xh)[i] = hi;
    ((uint32_t*)g_xlo)[i] = lo;
}

// ---------------- tensor-core dual GEMM: smem + ldmatrix + mma.sync ----------------
__device__ __forceinline__ void mma16816(float* c, const uint32_t* a, const uint32_t* b) {
    asm volatile(
        "mma.sync.aligned.m16n8k16.row.col.f32.bf16.bf16.f32 "
        "{%0,%1,%2,%3}, {%4,%5,%6,%7}, {%8,%9}, {%0,%1,%2,%3};"
        : "+f"(c[0]), "+f"(c[1]), "+f"(c[2]), "+f"(c[3])
        : "r"(a[0]), "r"(a[1]), "r"(a[2]), "r"(a[3]), "r"(b[0]), "r"(b[1]));
}

__device__ __forceinline__ void ldsm4(uint32_t* r, uint32_t addr) {
    asm volatile(
        "ldmatrix.sync.aligned.m8n8.x4.shared.b16 {%0,%1,%2,%3}, [%4];"
        : "=r"(r[0]), "=r"(r[1]), "=r"(r[2]), "=r"(r[3]) : "r"(addr));
}

// smem: A_hi[128][256B] @0, A_lo @32KB, B tiles @64KB (Wl_hi, Wl_lo, Wr_hi, Wr_lo)
// row = 256B = 16 chunks of 16B; swizzle: chunk c stored at c ^ (row & 7)
#define GEMM_SMEM 196608

__global__ void __launch_bounds__(512, 1) k_gemm_mma(int l) {
    extern __shared__ __align__(16) char sm[];
    int tid = threadIdx.x;
    int row0 = blockIdx.x * 128;

    // stage A (x_hi, x_lo): 128 rows x 16 chunks
    for (int i = tid; i < 2048; i += 512) {
        int r = i >> 4, c = i & 15;
        int gr = row0 + r;
        uint4 vh = make_uint4(0, 0, 0, 0), vl = make_uint4(0, 0, 0, 0);
        if (gr < NN) {
            vh = *(const uint4*)(g_xh + gr * D + c * 8);
            vl = *(const uint4*)(g_xlo + gr * D + c * 8);
        }
        int sc = c ^ (r & 7);
        *(uint4*)(sm + r * 256 + sc * 16) = vh;
        *(uint4*)(sm + 32768 + r * 256 + sc * 16) = vl;
    }
    // stage B: 4 tiles (Wl_hi, Wl_lo, Wr_hi, Wr_lo), each 128 n-rows x 16 chunks
    for (int i = tid; i < 8192; i += 512) {
        int tile = i >> 11, j = i & 2047;
        int n = j >> 4, c = j & 15;
        int mm = tile >> 1;
        const __nv_bfloat16* src = (tile & 1) ? g_wlo : g_whi;
        uint4 v = *(const uint4*)(src + ((l * 2 + mm) * D + n) * D + c * 8);
        int sc = c ^ (n & 7);
        *(uint4*)(sm + 65536 + tile * 32768 + n * 256 + sc * 16) = v;
    }
    __syncthreads();

    int wid = tid >> 5, lane = tid & 31;
    int rg = wid & 3;          // row group: rows rg*32 .. rg*32+31
    int cg = wid >> 2;         // col group: 0,1 -> xl ; 2,3 -> xr
    int m = cg >> 1;
    int colbase = (cg & 1) * 64;
    uint32_t sbase = (uint32_t)__cvta_generic_to_shared(sm);
    uint32_t sA_h = sbase;
    uint32_t sA_l = sbase + 32768;
    uint32_t sB_h = sbase + 65536 + (uint32_t)(m * 2) * 32768u;
    uint32_t sB_l = sB_h + 32768;

    float acc[2][8][4];
#pragma unroll
    for (int mt = 0; mt < 2; mt++)
#pragma unroll
        for (int nt = 0; nt < 8; nt++)
#pragma unroll
            for (int q = 0; q < 4; q++) acc[mt][nt][q] = 0.f;

    // ldmatrix lane address components
    int a_r = (lane & 7) + ((lane >> 3) & 1) * 8;  // mat0/2: rows 0-7, mat1/3: rows 8-15
    int a_c = lane >> 4;                           // mat0/1: k0 chunk, mat2/3: k8 chunk
    int b_n = (lane & 7) + (lane >> 4) * 8;        // mat0/1: n0-7, mat2/3: n8-15
    int b_c = (lane >> 3) & 1;                     // mat0/2: k0 chunk, mat1/3: k8 chunk

#pragma unroll
    for (int ks = 0; ks < 8; ks++) {
        uint32_t ah[2][4], al[2][4];
#pragma unroll
        for (int mt = 0; mt < 2; mt++) {
            int r = rg * 32 + mt * 16 + a_r;
            int c = 2 * ks + a_c;
            uint32_t off = (uint32_t)(r * 256 + ((c ^ (r & 7)) << 4));
            ldsm4(ah[mt], sA_h + off);
            ldsm4(al[mt], sA_l + off);
        }
#pragma unroll
        for (int ng = 0; ng < 4; ng++) {
            int n = colbase + ng * 16 + b_n;
            int c = 2 * ks + b_c;
            uint32_t off = (uint32_t)(n * 256 + ((c ^ (n & 7)) << 4));
            uint32_t bh[4], bl[4];
            ldsm4(bh, sB_h + off);
            ldsm4(bl, sB_l + off);
#pragma unroll
            for (int mt = 0; mt < 2; mt++) {
                mma16816(acc[mt][2 * ng], ah[mt], &bh[0]);
                mma16816(acc[mt][2 * ng], ah[mt], &bl[0]);
                mma16816(acc[mt][2 * ng], al[mt], &bh[0]);
                mma16816(acc[mt][2 * ng + 1], ah[mt], &bh[2]);
                mma16816(acc[mt][2 * ng + 1], ah[mt], &bl[2]);
                mma16816(acc[mt][2 * ng + 1], al[mt], &bh[2]);
            }
        }
    }

    float* dst = m ? g_xr : g_xl;
    int g = lane >> 2, t = lane & 3;
#pragma unroll
    for (int mt = 0; mt < 2; mt++) {
#pragma unroll
        for (int nt = 0; nt < 8; nt++) {
            int r0 = row0 + rg * 32 + mt * 16 + g;
            int cc = colbase + nt * 8 + 2 * t;
            if (r0 < NN)
                *(float2*)(dst + r0 * D + cc) = make_float2(acc[mt][nt][0], acc[mt][nt][1]);
            if (r0 + 8 < NN)
                *(float2*)(dst + (r0 + 8) * D + cc) = make_float2(acc[mt][nt][2], acc[mt][nt][3]);
        }
    }
}

// ---------------- per-node GATv2: 16-lane groups, 2 edges in flight ----------------
__device__ __forceinline__ float lrelu(float z) {
    return z > 0.f ? z : NEG * z;
}

__global__ void __launch_bounds__(64) k_node(const float* __restrict__ att,
                                             const float* __restrict__ bias) {
    int node = blockIdx.x * 2 + (threadIdx.x >> 5);
    if (node >= NN) return;
    int lane = threadIdx.x & 31;
    int l16 = lane & 15;
    int grp = lane >> 4;
    const unsigned gmask = 0xFFFFu << (grp << 4);
    int beg = g_off[node], end = g_off[node + 1];

    const float4* xr4 = (const float4*)(g_xr + node * 128 + l16 * 8);
    float4 xr0 = xr4[0], xr1 = xr4[1];
    const float4* at4 = (const float4*)(att + l16 * 8);
    float4 a0 = at4[0], a1 = at4[1];

    float m = -1e30f, sum = 0.f;
    float4 acc0 = make_float4(0.f, 0.f, 0.f, 0.f);
    float4 acc1 = make_float4(0.f, 0.f, 0.f, 0.f);

    for (int p = beg + grp; p < end; p += 2) {
        int s = g_srcs[p];
        const float4* v4 = (const float4*)(g_xl + s * 128 + l16 * 8);
        float4 v0 = v4[0], v1 = v4[1];
        float d = lrelu(v0.x + xr0.x) * a0.x;
        d = fmaf(lrelu(v0.y + xr0.y), a0.y, d);
        d = fmaf(lrelu(v0.z + xr0.z), a0.z, d);
        d = fmaf(lrelu(v0.w + xr0.w), a0.w, d);
        d = fmaf(lrelu(v1.x + xr1.x), a1.x, d);
        d = fmaf(lrelu(v1.y + xr1.y), a1.y, d);
        d = fmaf(lrelu(v1.z + xr1.z), a1.z, d);
        d = fmaf(lrelu(v1.w + xr1.w), a1.w, d);
#pragma unroll
        for (int o = 1; o < 16; o <<= 1) d += __shfl_xor_sync(gmask, d, o);
        float mn = fmaxf(m, d);
        float c = __expf(m - mn);
        float w = __expf(d - mn);
        sum = sum * c + w;
        acc0.x = fmaf(acc0.x, c, w * v0.x);
        acc0.y = fmaf(acc0.y, c, w * v0.y);
        acc0.z = fmaf(acc0.z, c, w * v0.z);
        acc0.w = fmaf(acc0.w, c, w * v0.w);
        acc1.x = fmaf(acc1.x, c, w * v1.x);
        acc1.y = fmaf(acc1.y, c, w * v1.y);
        acc1.z = fmaf(acc1.z, c, w * v1.z);
        acc1.w = fmaf(acc1.w, c, w * v1.w);
        m = mn;
    }
    __syncwarp();
    float mo = __shfl_xor_sync(0xffffffffu, m, 16);
    float so = __shfl_xor_sync(0xffffffffu, sum, 16);
    float ms = fmaxf(m, mo);
    float cme = __expf(m - ms);
    float sum_t = fmaf(so, __expf(mo - ms), sum * cme);
    acc0.x *= cme; acc0.y *= cme; acc0.z *= cme; acc0.w *= cme;
    acc1.x *= cme; acc1.y *= cme; acc1.z *= cme; acc1.w *= cme;
    acc0.x += __shfl_xor_sync(0xffffffffu, acc0.x, 16);
    acc0.y += __shfl_xor_sync(0xffffffffu, acc0.y, 16);
    acc0.z += __shfl_xor_sync(0xffffffffu, acc0.z, 16);
    acc0.w += __shfl_xor_sync(0xffffffffu, acc0.w, 16);
    acc1.x += __shfl_xor_sync(0xffffffffu, acc1.x, 16);
    acc1.y += __shfl_xor_sync(0xffffffffu, acc1.y, 16);
    acc1.z += __shfl_xor_sync(0xffffffffu, acc1.z, 16);
    acc1.w += __shfl_xor_sync(0xffffffffu, acc1.w, 16);
    if (grp == 0) {
        float inv = 1.f / (sum_t + 1e-16f);
        const float4* b4 = (const float4*)(bias + l16 * 8);
        float4 b0 = b4[0], b1 = b4[1];
        float4 o0, o1;
        o0.x = fmaf(acc0.x, inv, b0.x);
        o0.y = fmaf(acc0.y, inv, b0.y);
        o0.z = fmaf(acc0.z, inv, b0.z);
        o0.w = fmaf(acc0.w, inv, b0.w);
        o1.x = fmaf(acc1.x, inv, b1.x);
        o1.y = fmaf(acc1.y, inv, b1.y);
        o1.z = fmaf(acc1.z, inv, b1.z);
        o1.w = fmaf(acc1.w, inv, b1.w);
        float4* op = (float4*)(g_out + node * 128 + l16 * 8);
        op[0] = o0;
        op[1] = o1;
    }
}

// ---------------- BatchNorm stats + BN->GELU apply ----------------
__global__ void k_zero_cols() {
    g_colsum[threadIdx.x] = 0.f;
    g_colsq[threadIdx.x] = 0.f;
}

__global__ void k_bn() {
    int tid = threadIdx.x;
    int c4 = tid & 31;
    int rg = tid >> 5;
    float4 s = make_float4(0.f, 0.f, 0.f, 0.f);
    float4 q = make_float4(0.f, 0.f, 0.f, 0.f);
    for (int r = blockIdx.x * 8 + rg; r < NN; r += gridDim.x * 8) {
        float4 v = ((const float4*)g_out)[r * 32 + c4];
        s.x += v.x; s.y += v.y; s.z += v.z; s.w += v.w;
        q.x = fmaf(v.x, v.x, q.x); q.y = fmaf(v.y, v.y, q.y);
        q.z = fmaf(v.z, v.z, q.z); q.w = fmaf(v.w, v.w, q.w);
    }
    __shared__ float shs[8][32][4];
    __shared__ float shq[8][32][4];
    shs[rg][c4][0] = s.x; shs[rg][c4][1] = s.y; shs[rg][c4][2] = s.z; shs[rg][c4][3] = s.w;
    shq[rg][c4][0] = q.x; shq[rg][c4][1] = q.y; shq[rg][c4][2] = q.z; shq[rg][c4][3] = q.w;
    __syncthreads();
    if (tid < 128) {
        int col = tid;
        int cc4 = col >> 2, ce = col & 3;
        float ts = 0.f, tq = 0.f;
#pragma unroll
        for (int g = 0; g < 8; g++) {
            ts += shs[g][cc4][ce];
            tq += shq[g][cc4][ce];
        }
        atomicAdd(&g_colsum[col], ts);
        atomicAdd(&g_colsq[col], tq);
    }
}

// BN + erf-GELU; final layer -> fp32 d_out, else -> split bf16 for next GEMM
__global__ void k_bnapply(const float* __restrict__ gamma,
                          const float* __restrict__ beta,
                          float* __restrict__ dptr) {
    int i = blockIdx.x * 256 + threadIdx.x;  // over NN*32 float4s
    if (i >= NN * 32) return;
    int c4 = (i & 31) * 4;
    const float invN = 1.f / (float)NN;
    float4 v = ((const float4*)g_out)[i];
    float o[4];
    float vin[4] = {v.x, v.y, v.z, v.w};
#pragma unroll
    for (int c = 0; c < 4; c++) {
        float mu = g_colsum[c4 + c] * invN;
        float var = g_colsq[c4 + c] * invN - mu * mu;
        float y = gamma[c4 + c] * (vin[c] - mu) * rsqrtf(var + BNEPS) + beta[c4 + c];
        o[c] = 0.5f * y * (1.f + erff(y * 0.70710678118654752f));
    }
    if (dptr) {
        ((float4*)dptr)[i] = make_float4(o[0], o[1], o[2], o[3]);
    } else {
        uint32_t h0, l0, h1, l1;
        split2(o[0], o[1], h0, l0);
        split2(o[2], o[3], h1, l1);
        ((uint2*)g_xh)[i] = make_uint2(h0, h1);
        ((uint2*)g_xlo)[i] = make_uint2(l0, l1);
    }
}

// ---------------- launch ----------------
extern "C" void kernel_launch(void* const* d_in, const int* in_sizes, int n_in,
                              void* d_out, int out_size) {
    const float* x = (const float*)d_in[0];
    const int* ei = (const int*)d_in[1];
    const float* Wl = (const float*)d_in[2];
    const float* Wr = (const float*)d_in[3];
    const float* att = (const float*)d_in[4];
    const float* bias = (const float*)d_in[5];
    const float* gamma = (const float*)d_in[6];
    const float* beta = (const float*)d_in[7];
    float* outp = (float*)d_out;

    cudaFuncSetAttribute(k_gemm_mma, cudaFuncAttributeMaxDynamicSharedMemorySize, GEMM_SMEM);

    const int gemm_blocks = (NN + 127) / 128;

    // launches 1-2: conversions; 3: detect+zero; 4: layer-0 GEMM (profiled slot)
    k_cvt_w<<<(3 * 2 * D * D + 255) / 256, 256>>>(Wl, Wr);
    k_cvt_x<<<(NN * 64 + 255) / 256, 256>>>(x);
    k_detect_zero<<<SB, 256>>>(ei);
    k_gemm_mma<<<gemm_blocks, 512, GEMM_SMEM>>>(0);

    // CSR by dst
    k_hist<<<(NE + 255) / 256, 256>>>(ei);
    k_part<<<SB, 256>>>();
    k_scanpart<<<1, 256>>>();
    k_off<<<SB, 256>>>();
    k_scatter<<<(NE + 255) / 256, 256>>>(ei);

    for (int l = 0; l < 3; l++) {
        if (l > 0) k_gemm_mma<<<gemm_blocks, 512, GEMM_SMEM>>>(l);
        k_node<<<(NN + 1) / 2, 64>>>(att + l * D, bias + l * D);
        k_zero_cols<<<1, 128>>>();
        k_bn<<<296, 256>>>();
        float* dst = (l == 2) ? outp : nullptr;
        k_bnapply<<<(NN * 32 + 255) / 256, 256>>>(gamma + l * D, beta + l * D, dst);
    }
}